// round 16
// baseline (speedup 1.0000x reference)
#include <cuda_runtime.h>

// RVOModule on GB300. B=256, N=1024, K=32.
// R16 = R15 with BPB=8: block owns 128 peds (warp does 2 passes), grid 2048.
// Finer work quantum -> smaller wave-tail imbalance; staging redundancy paid
// for out of DRAM headroom.

#define TAU 3.0f
#define FIX 0.2f

#define NPED 1024
#define KNEI 32
#define BPB 8                 // blocks per batch
#define THREADS 512           // threads per block
#define PEDS_PER_BLOCK (NPED / BPB)                    // 128
#define PASSES (PEDS_PER_BLOCK / (THREADS / 32) / 4)   // 2

typedef unsigned long long f32x2;

__device__ __forceinline__ f32x2 pk(float lo, float hi) {
    f32x2 r; asm("mov.b64 %0, {%1, %2};" : "=l"(r) : "f"(lo), "f"(hi)); return r;
}
__device__ __forceinline__ void upk(float& lo, float& hi, f32x2 v) {
    asm("mov.b64 {%0, %1}, %2;" : "=f"(lo), "=f"(hi) : "l"(v));
}
__device__ __forceinline__ f32x2 sub2(f32x2 a, f32x2 b) {
    f32x2 r; asm("sub.rn.f32x2 %0, %1, %2;" : "=l"(r) : "l"(a), "l"(b)); return r;
}
__device__ __forceinline__ f32x2 mul2(f32x2 a, f32x2 b) {
    f32x2 r; asm("mul.rn.f32x2 %0, %1, %2;" : "=l"(r) : "l"(a), "l"(b)); return r;
}
__device__ __forceinline__ f32x2 fma2(f32x2 a, f32x2 b, f32x2 c) {
    f32x2 r; asm("fma.rn.f32x2 %0, %1, %2, %3;" : "=l"(r) : "l"(a), "l"(b), "l"(c)); return r;
}
__device__ __forceinline__ float rsqrt_approx(float x) {
    float r; asm("rsqrt.approx.f32 %0, %1;" : "=f"(r) : "f"(x)); return r;
}

__device__ __forceinline__ void interact_pair(
    const f32x2 sfx2, const f32x2 sfy2, const f32x2 vdx2, const f32x2 vdy2,
    const float4 qa, const float4 qb, const float ma, const float mb,
    const float thr2, const f32x2 eps2, f32x2& accX, f32x2& accY)
{
    const f32x2 qx2 = pk(qa.x, qb.x);
    const f32x2 qy2 = pk(qa.y, qb.y);
    const f32x2 qz2 = pk(qa.z, qb.z);
    const f32x2 qw2 = pk(qa.w, qb.w);

    const f32x2 rpx2 = sub2(sfx2, qx2);
    const f32x2 rpy2 = sub2(sfy2, qy2);
    const f32x2 rvx2 = sub2(vdx2, qz2);
    const f32x2 rvy2 = sub2(vdy2, qw2);

    const f32x2 dpv2 = fma2(rpx2, rvx2, mul2(rpy2, rvy2));
    const f32x2 dvv2 = fma2(rvx2, rvx2, fma2(rvy2, rvy2, eps2));

    float dp0, dp1, dv0, dv1;
    upk(dp0, dp1, dpv2);
    upk(dv0, dv1, dvv2);
    float t0 = __fdividef(dp0, dv0);
    float t1 = __fdividef(dp1, dv1);
    t0 = fminf(fmaxf(t0, 0.0f), TAU);
    t1 = fminf(fmaxf(t1, 0.0f), TAU);
    const f32x2 t2 = pk(t0, t1);

    const f32x2 dx2   = fma2(t2, rvx2, rpx2);
    const f32x2 dy2   = fma2(t2, rvy2, rpy2);
    const f32x2 md2_2 = fma2(dx2, dx2, mul2(dy2, dy2));     // min_dist^2
    const f32x2 s2    = fma2(rpx2, rpx2, mul2(rpy2, rpy2)); // |rel_pos|^2

    float md0, md1, s0, s1;
    upk(md0, md1, md2_2);
    upk(s0, s1, s2);

    // m in {0,1}: thr2*m==0 -> md2<0 never true -> contrib 0 (matches ref).
    // s==0 (self, m==1): rp==0 -> contrib 0 * finite = 0 (matches ref).
    const float inv0 = (md0 < thr2 * ma) ? rsqrt_approx(fmaxf(s0, 1e-30f)) : 0.0f;
    const float inv1 = (md1 < thr2 * mb) ? rsqrt_approx(fmaxf(s1, 1e-30f)) : 0.0f;
    const f32x2 inv2 = pk(inv0, inv1);

    accX = fma2(rpx2, inv2, accX);
    accY = fma2(rpy2, inv2, accY);
}

__global__ __launch_bounds__(THREADS, 2)
void rvo_kernel(const float2* __restrict__ p_cur,
                const float2* __restrict__ v_cur,
                const float2* __restrict__ v_desire,
                const int*    __restrict__ near_idx,
                const float*  __restrict__ neigh_mask,
                const int*    __restrict__ thr_ptr,
                float2*       __restrict__ out)
{
    __shared__ float4 pv[NPED];               // whole batch {p,v}, 16 KB
    __shared__ float2 vds[PEDS_PER_BLOCK];    // v_desire for block's peds, 1 KB

    const int b       = blockIdx.x / BPB;
    const int sub     = blockIdx.x % BPB;
    const int base    = b * NPED;
    const int pedbase = sub * PEDS_PER_BLOCK;

    #pragma unroll
    for (int i = threadIdx.x; i < NPED; i += THREADS) {
        const float2 p = p_cur[base + i];
        const float2 v = v_cur[base + i];
        pv[i] = make_float4(p.x, p.y, v.x, v.y);
    }
    if (threadIdx.x < PEDS_PER_BLOCK)
        vds[threadIdx.x] = v_desire[base + pedbase + threadIdx.x];
    __syncthreads();

    const int warp = threadIdx.x >> 5;
    const int lane = threadIdx.x & 31;
    const int grp  = lane >> 3;            // ped (0..3) within a pass
    const int q8   = lane & 7;

    const float thrF = (float)(*thr_ptr);
    const float thr2 = thrF * thrF;
    const f32x2 eps2 = pk(2e-6f, 2e-6f);   // ref: (+1e-6)+1e-6 folded

    const int wped = warp * (PASSES * 4);  // warp's first ped within block (8/warp)
    const int nb   = pedbase + wped;       // within-batch id of warp's first ped
    const int g0   = base + nb;            // global id

    const int4*   idx4 = (const int4*)  (near_idx)   + (long long)g0 * (KNEI / 4) + lane;
    const float4* msk4 = (const float4*)(neigh_mask) + (long long)g0 * (KNEI / 4) + lane;

    // Prologue: pass 0's loads.
    int4   j4 = idx4[0];
    float4 m4 = msk4[0];

    // Four independent persistent gather registers (predicated LDS keeps
    // stale finite values; the m==0 collision test discards garbage).
    float4 q0 = make_float4(0.f, 0.f, 0.f, 0.f);
    float4 q1 = q0, q2 = q0, q3 = q0;

    #pragma unroll 1
    for (int c = 0; c < PASSES; ++c) {
        int4 jn; float4 mn;
        if (c < PASSES - 1) { jn = idx4[(c + 1) * 32]; mn = msk4[(c + 1) * 32]; }

        const int pl = c * 4 + grp;        // ped offset within warp's range
        const float4 sf = pv[nb + pl];
        const float2 vd = vds[wped + pl];

        const f32x2 sfx2 = pk(sf.x, sf.x);
        const f32x2 sfy2 = pk(sf.y, sf.y);
        const f32x2 vdx2 = pk(vd.x, vd.x);
        const f32x2 vdy2 = pk(vd.y, vd.y);

        // All four predicated gathers issued up front (independent regs).
        if (m4.x != 0.0f) q0 = pv[j4.x];
        if (m4.y != 0.0f) q1 = pv[j4.y];
        if (m4.z != 0.0f) q2 = pv[j4.z];
        if (m4.w != 0.0f) q3 = pv[j4.w];

        f32x2 accX = 0ull, accY = 0ull;
        interact_pair(sfx2, sfy2, vdx2, vdy2, q0, q1, m4.x, m4.y,
                      thr2, eps2, accX, accY);
        interact_pair(sfx2, sfy2, vdx2, vdy2, q2, q3, m4.z, m4.w,
                      thr2, eps2, accX, accY);

        float ax0, ax1, ay0, ay1;
        upk(ax0, ax1, accX);
        upk(ay0, ay1, accY);
        float cx = -ay0 - ay1;             // cx = -Σ rpy·inv
        float cy =  ax0 + ax1;             // cy = +Σ rpx·inv

        #pragma unroll
        for (int o = 1; o < 8; o <<= 1) {
            cx += __shfl_xor_sync(0xffffffffu, cx, o);
            cy += __shfl_xor_sync(0xffffffffu, cy, o);
        }

        if (q8 == 0) {
            out[g0 + pl] = make_float2(vd.x + cx * FIX, vd.y + cy * FIX);
        }

        j4 = jn;
        m4 = mn;
    }
}

extern "C" void kernel_launch(void* const* d_in, const int* in_sizes, int n_in,
                              void* d_out, int out_size)
{
    const float2* p_cur    = (const float2*)d_in[0];
    const float2* v_cur    = (const float2*)d_in[1];
    const float2* v_desire = (const float2*)d_in[2];
    const int*    near_idx = (const int*)d_in[3];
    const float*  mask     = (const float*)d_in[4];
    const int*    thr      = (const int*)d_in[5];
    float2*       out      = (float2*)d_out;

    const int P = in_sizes[0] / 2;          // B*N pedestrians
    const int nBatches = P / NPED;          // 256
    const int blocks = nBatches * BPB;      // 2048

    rvo_kernel<<<blocks, THREADS>>>(p_cur, v_cur, v_desire, near_idx, mask, thr, out);
}

// round 17
// speedup vs baseline: 1.1100x; 1.1100x over previous
#include <cuda_runtime.h>

// RVOModule on GB300. B=256, N=1024, K=32.
// R17 = R15 (BPB=4 granularity optimum, smem staging, predicated gathers,
// packed f32x2 math) + 256-bit ld.global.v8 idx/mask loads enabling a
// 4-lanes-per-pedestrian layout: lane owns 8 neighbors of ONE ped,
// 8 peds per double-pass, 2-level shuffle reduction (was 3-level).

#define TAU 3.0f
#define FIX 0.2f

#define NPED 1024
#define KNEI 32
#define BPB 4                 // blocks per batch
#define THREADS 512           // threads per block
#define PEDS_PER_BLOCK (NPED / BPB)        // 256; warp owns 16 peds

typedef unsigned long long f32x2;
typedef unsigned int uint32;

__device__ __forceinline__ f32x2 pk(float lo, float hi) {
    f32x2 r; asm("mov.b64 %0, {%1, %2};" : "=l"(r) : "f"(lo), "f"(hi)); return r;
}
__device__ __forceinline__ void upk(float& lo, float& hi, f32x2 v) {
    asm("mov.b64 {%0, %1}, %2;" : "=f"(lo), "=f"(hi) : "l"(v));
}
__device__ __forceinline__ f32x2 sub2(f32x2 a, f32x2 b) {
    f32x2 r; asm("sub.rn.f32x2 %0, %1, %2;" : "=l"(r) : "l"(a), "l"(b)); return r;
}
__device__ __forceinline__ f32x2 mul2(f32x2 a, f32x2 b) {
    f32x2 r; asm("mul.rn.f32x2 %0, %1, %2;" : "=l"(r) : "l"(a), "l"(b)); return r;
}
__device__ __forceinline__ f32x2 fma2(f32x2 a, f32x2 b, f32x2 c) {
    f32x2 r; asm("fma.rn.f32x2 %0, %1, %2, %3;" : "=l"(r) : "l"(a), "l"(b), "l"(c)); return r;
}
__device__ __forceinline__ float rsqrt_approx(float x) {
    float r; asm("rsqrt.approx.f32 %0, %1;" : "=f"(r) : "f"(x)); return r;
}
// 256-bit global load (sm_100+): one instruction, 32B per lane.
__device__ __forceinline__ void ldg_v8(const void* p, uint32 r[8]) {
    asm("ld.global.nc.v8.b32 {%0,%1,%2,%3,%4,%5,%6,%7}, [%8];"
        : "=r"(r[0]), "=r"(r[1]), "=r"(r[2]), "=r"(r[3]),
          "=r"(r[4]), "=r"(r[5]), "=r"(r[6]), "=r"(r[7])
        : "l"(p));
}

__device__ __forceinline__ void interact_pair(
    const f32x2 sfx2, const f32x2 sfy2, const f32x2 vdx2, const f32x2 vdy2,
    const float4 qa, const float4 qb, const float ma, const float mb,
    const float thr2, const f32x2 eps2, f32x2& accX, f32x2& accY)
{
    const f32x2 qx2 = pk(qa.x, qb.x);
    const f32x2 qy2 = pk(qa.y, qb.y);
    const f32x2 qz2 = pk(qa.z, qb.z);
    const f32x2 qw2 = pk(qa.w, qb.w);

    const f32x2 rpx2 = sub2(sfx2, qx2);
    const f32x2 rpy2 = sub2(sfy2, qy2);
    const f32x2 rvx2 = sub2(vdx2, qz2);
    const f32x2 rvy2 = sub2(vdy2, qw2);

    const f32x2 dpv2 = fma2(rpx2, rvx2, mul2(rpy2, rvy2));
    const f32x2 dvv2 = fma2(rvx2, rvx2, fma2(rvy2, rvy2, eps2));

    float dp0, dp1, dv0, dv1;
    upk(dp0, dp1, dpv2);
    upk(dv0, dv1, dvv2);
    float t0 = __fdividef(dp0, dv0);
    float t1 = __fdividef(dp1, dv1);
    t0 = fminf(fmaxf(t0, 0.0f), TAU);
    t1 = fminf(fmaxf(t1, 0.0f), TAU);
    const f32x2 t2 = pk(t0, t1);

    const f32x2 dx2   = fma2(t2, rvx2, rpx2);
    const f32x2 dy2   = fma2(t2, rvy2, rpy2);
    const f32x2 md2_2 = fma2(dx2, dx2, mul2(dy2, dy2));     // min_dist^2
    const f32x2 s2    = fma2(rpx2, rpx2, mul2(rpy2, rpy2)); // |rel_pos|^2

    float md0, md1, s0, s1;
    upk(md0, md1, md2_2);
    upk(s0, s1, s2);

    // m in {0,1}: thr2*m==0 -> md2<0 never true -> contrib 0 (matches ref).
    // s==0 (self, m==1): rp==0 -> contrib 0 * finite = 0 (matches ref).
    const float inv0 = (md0 < thr2 * ma) ? rsqrt_approx(fmaxf(s0, 1e-30f)) : 0.0f;
    const float inv1 = (md1 < thr2 * mb) ? rsqrt_approx(fmaxf(s1, 1e-30f)) : 0.0f;
    const f32x2 inv2 = pk(inv0, inv1);

    accX = fma2(rpx2, inv2, accX);
    accY = fma2(rpy2, inv2, accY);
}

__global__ __launch_bounds__(THREADS, 2)
void rvo_kernel(const float2* __restrict__ p_cur,
                const float2* __restrict__ v_cur,
                const float2* __restrict__ v_desire,
                const int*    __restrict__ near_idx,
                const float*  __restrict__ neigh_mask,
                const int*    __restrict__ thr_ptr,
                float2*       __restrict__ out)
{
    __shared__ float4 pv[NPED];               // whole batch {p,v}, 16 KB
    __shared__ float2 vds[PEDS_PER_BLOCK];    // v_desire for block's peds, 2 KB

    const int b       = blockIdx.x / BPB;
    const int sub     = blockIdx.x % BPB;
    const int base    = b * NPED;
    const int pedbase = sub * PEDS_PER_BLOCK;

    #pragma unroll
    for (int i = threadIdx.x; i < NPED; i += THREADS) {
        const float2 p = p_cur[base + i];
        const float2 v = v_cur[base + i];
        pv[i] = make_float4(p.x, p.y, v.x, v.y);
    }
    if (threadIdx.x < PEDS_PER_BLOCK)
        vds[threadIdx.x] = v_desire[base + pedbase + threadIdx.x];
    __syncthreads();

    const int warp = threadIdx.x >> 5;
    const int lane = threadIdx.x & 31;

    const float thrF = (float)(*thr_ptr);
    const float thr2 = thrF * thrF;
    const f32x2 eps2 = pk(2e-6f, 2e-6f);   // ref: (+1e-6)+1e-6 folded

    const int wped = warp * 16;            // warp's first ped within block
    const int nb   = pedbase + wped;       // within-batch id
    const int g0   = base + nb;            // global id

    // Warp's contiguous neighbor-list region: 16 peds * 128B = 2048B,
    // covered by 2 double-passes of 1024B each. 32B-aligned per lane.
    const char* ibase = (const char*)near_idx   + (long long)g0 * (KNEI * 4);
    const char* mbase = (const char*)neigh_mask + (long long)g0 * (KNEI * 4);
    const int laneByte = lane * 32;

    // Persistent gather registers (predicated LDS keeps stale finite values;
    // the m==0 collision test discards any garbage math).
    float4 q0 = make_float4(0.f, 0.f, 0.f, 0.f);
    float4 q1 = q0, q2 = q0, q3 = q0;

    #pragma unroll 1
    for (int d = 0; d < 2; ++d) {
        // One 256-bit load each: lane gets quads 2*lane, 2*lane+1 of the
        // 1024B double-pass block = 8 neighbors of ped (lane>>2).
        uint32 jr[8], mr[8];
        ldg_v8(ibase + d * 1024 + laneByte, jr);
        ldg_v8(mbase + d * 1024 + laneByte, mr);

        const int pl = d * 8 + (lane >> 2);    // ped offset within warp's 16
        const float4 sf = pv[nb + pl];         // broadcast to 4 lanes
        const float2 vd = vds[wped + pl];

        const f32x2 sfx2 = pk(sf.x, sf.x);
        const f32x2 sfy2 = pk(sf.y, sf.y);
        const f32x2 vdx2 = pk(vd.x, vd.x);
        const f32x2 vdy2 = pk(vd.y, vd.y);

        f32x2 accX = 0ull, accY = 0ull;

        // First quad (neighbors 0..3 of lane's 8).
        {
            const float m0 = __uint_as_float(mr[0]);
            const float m1 = __uint_as_float(mr[1]);
            const float m2 = __uint_as_float(mr[2]);
            const float m3 = __uint_as_float(mr[3]);
            if (m0 != 0.0f) q0 = pv[jr[0]];
            if (m1 != 0.0f) q1 = pv[jr[1]];
            if (m2 != 0.0f) q2 = pv[jr[2]];
            if (m3 != 0.0f) q3 = pv[jr[3]];
            interact_pair(sfx2, sfy2, vdx2, vdy2, q0, q1, m0, m1,
                          thr2, eps2, accX, accY);
            interact_pair(sfx2, sfy2, vdx2, vdy2, q2, q3, m2, m3,
                          thr2, eps2, accX, accY);
        }
        // Second quad (neighbors 4..7).
        {
            const float m0 = __uint_as_float(mr[4]);
            const float m1 = __uint_as_float(mr[5]);
            const float m2 = __uint_as_float(mr[6]);
            const float m3 = __uint_as_float(mr[7]);
            if (m0 != 0.0f) q0 = pv[jr[4]];
            if (m1 != 0.0f) q1 = pv[jr[5]];
            if (m2 != 0.0f) q2 = pv[jr[6]];
            if (m3 != 0.0f) q3 = pv[jr[7]];
            interact_pair(sfx2, sfy2, vdx2, vdy2, q0, q1, m0, m1,
                          thr2, eps2, accX, accY);
            interact_pair(sfx2, sfy2, vdx2, vdy2, q2, q3, m2, m3,
                          thr2, eps2, accX, accY);
        }

        float ax0, ax1, ay0, ay1;
        upk(ax0, ax1, accX);
        upk(ay0, ay1, accY);
        float cx = -ay0 - ay1;                 // cx = -Σ rpy·inv
        float cy =  ax0 + ax1;                 // cy = +Σ rpx·inv

        // 2-level reduction across the 4 lanes sharing this pedestrian.
        #pragma unroll
        for (int o = 1; o < 4; o <<= 1) {
            cx += __shfl_xor_sync(0xffffffffu, cx, o);
            cy += __shfl_xor_sync(0xffffffffu, cy, o);
        }

        if ((lane & 3) == 0) {
            out[g0 + pl] = make_float2(vd.x + cx * FIX, vd.y + cy * FIX);
        }
    }
}

extern "C" void kernel_launch(void* const* d_in, const int* in_sizes, int n_in,
                              void* d_out, int out_size)
{
    const float2* p_cur    = (const float2*)d_in[0];
    const float2* v_cur    = (const float2*)d_in[1];
    const float2* v_desire = (const float2*)d_in[2];
    const int*    near_idx = (const int*)d_in[3];
    const float*  mask     = (const float*)d_in[4];
    const int*    thr      = (const int*)d_in[5];
    float2*       out      = (float2*)d_out;

    const int P = in_sizes[0] / 2;          // B*N pedestrians
    const int nBatches = P / NPED;          // 256
    const int blocks = nBatches * BPB;      // 1024

    rvo_kernel<<<blocks, THREADS>>>(p_cur, v_cur, v_desire, near_idx, mask, thr, out);
}